// round 6
// baseline (speedup 1.0000x reference)
#include <cuda_runtime.h>
#include <cuda_fp16.h>
#include <stdint.h>

#define R_NODES   256
#define N_STEPS   512
#define M_SAMP    512
#define OUT_DIM   10
#define LUT_WORDS 8192            // 2^18 bits / 32
#define NPC       8               // samples per cluster
#define N_CTA     128             // 64 clusters x 2 CTAs (node-split)
#define RB_STRIDE 264             // halfs per sample row (conflict-free B-frag LDS)
#define MAGIC_F   8388608.0f      // 2^23 mantissa trick: float bits low 23 = integer sum

// Scratch: __device__ globals (no allocation allowed)
__device__ unsigned g_lut_bits[R_NODES * LUT_WORDS]; // 8 MB bit-packed LUT
__device__ unsigned g_x_bits[M_SAMP * N_STEPS];      // 1 MB bit-packed inputs

// ---------------------------------------------------------------------------
// Pack LUT (flat): word w, bit b = lut[w*32 + b]. MLP=32 load stage then ballots.
// ---------------------------------------------------------------------------
__global__ void pack_lut_kernel(const int* __restrict__ lut) {
    const int warp_g = (blockIdx.x * blockDim.x + threadIdx.x) >> 5;
    const int lane   = threadIdx.x & 31;
    const int w0     = warp_g * 32;
    const unsigned* src = (const unsigned*)lut;
    unsigned v[32];
    #pragma unroll
    for (int i = 0; i < 32; i++)
        v[i] = src[(size_t)(w0 + i) * 32 + lane];
    unsigned myw = 0;
    #pragma unroll
    for (int i = 0; i < 32; i++) {
        unsigned b = __ballot_sync(0xFFFFFFFFu, v[i] & 1u);
        if (i == lane) myw = b;
    }
    g_lut_bits[w0 + lane] = myw;
}

// ---------------------------------------------------------------------------
// Pack x: int32[512][512][4][8] (0/1) -> g_x_bits[m*512 + t], bit i = feature i
// ---------------------------------------------------------------------------
__global__ void pack_x_kernel(const int* __restrict__ x) {
    int w = blockIdx.x * blockDim.x + threadIdx.x;
    if (w >= M_SAMP * N_STEPS) return;
    const uint4* p = (const uint4*)(x + (size_t)w * 32);
    unsigned word = 0;
    #pragma unroll
    for (int j = 0; j < 8; j++) {
        uint4 v = p[j];
        word |= (v.x & 1u) << (4 * j + 0);
        word |= (v.y & 1u) << (4 * j + 1);
        word |= (v.z & 1u) << (4 * j + 2);
        word |= (v.w & 1u) << (4 * j + 3);
    }
    g_x_bits[w] = word;
}

// ---------------------------------------------------------------------------
// m16n8k16 fp16 MMA, fp32 accumulate (exact for our integer ranges)
// ---------------------------------------------------------------------------
__device__ __forceinline__ void mma16816(float* d, const unsigned* a, unsigned b0, unsigned b1) {
    asm volatile(
        "mma.sync.aligned.m16n8k16.row.col.f32.f16.f16.f32 "
        "{%0,%1,%2,%3}, {%4,%5,%6,%7}, {%8,%9}, {%0,%1,%2,%3};\n"
        : "+f"(d[0]), "+f"(d[1]), "+f"(d[2]), "+f"(d[3])
        : "r"(a[0]), "r"(a[1]), "r"(a[2]), "r"(a[3]), "r"(b0), "r"(b1));
}

// ---------------------------------------------------------------------------
// Cluster / mbarrier helpers
// ---------------------------------------------------------------------------
__device__ __forceinline__ uint32_t smem_u32(const void* p) {
    uint32_t a;
    asm("{ .reg .u64 t; cvta.to.shared.u64 t, %1; cvt.u32.u64 %0, t; }" : "=r"(a) : "l"(p));
    return a;
}
__device__ __forceinline__ uint32_t mapa_u32(uint32_t laddr, uint32_t rank) {
    uint32_t r;
    asm("mapa.shared::cluster.u32 %0, %1, %2;" : "=r"(r) : "r"(laddr), "r"(rank));
    return r;
}
__device__ __forceinline__ void st_cluster_u16(uint32_t addr, unsigned short v) {
    asm volatile("st.shared::cluster.b16 [%0], %1;" :: "r"(addr), "h"(v) : "memory");
}
#define MBAR_INIT(mb, c)  asm volatile("mbarrier.init.shared.b64 [%0], %1;" :: "r"(mb), "r"(c) : "memory")
__device__ __forceinline__ void mbar_arrive_local(uint32_t mb) {
    asm volatile("mbarrier.arrive.release.cluster.shared::cta.b64 _, [%0];" :: "r"(mb) : "memory");
}
__device__ __forceinline__ void mbar_arrive_remote(uint32_t mb_remote) {
    asm volatile("mbarrier.arrive.release.cluster.shared::cluster.b64 _, [%0];" :: "r"(mb_remote) : "memory");
}
__device__ __forceinline__ void mbar_wait_cluster(uint32_t mb, uint32_t parity) {
    asm volatile(
        "{\n\t.reg .pred P;\n"
        "W%=:\n\t"
        "mbarrier.try_wait.parity.acquire.cluster.shared::cta.b64 P, [%0], %1, 0x989680;\n\t"
        "@!P bra W%=;\n\t}"
        :: "r"(mb), "r"(parity) : "memory");
}
#define CLUSTER_SYNC() do { \
    asm volatile("barrier.cluster.arrive.aligned;" ::: "memory"); \
    asm volatile("barrier.cluster.wait.aligned;"   ::: "memory"); \
} while (0)

// ---------------------------------------------------------------------------
// Reservoir kernel: 128 CTAs as 64 clusters of 2. Cluster c owns samples
// [8c, 8c+8); CTA rank r computes nodes [128r, 128r+128). Per step: warp w
// computes one m16n8k16 tile chain over its 16 nodes (A in registers, exact
// fp16/fp32 integer math, magic-mantissa F2I), gathers bit-packed LUT words
// from L2, writes new fp16 state into BOTH CTAs' double-buffered state tiles
// (local STS + DSMEM st.shared::cluster), then a count=2 mbarrier handshake.
// ---------------------------------------------------------------------------
__global__ void __launch_bounds__(256, 1) __cluster_dims__(2, 1, 1)
reservoir_kernel(const int* __restrict__ input_nodes,
                 const int* __restrict__ Wres,
                 const int* __restrict__ primes,
                 const int* __restrict__ init_res,
                 const float* __restrict__ readout_W,
                 const float* __restrict__ readout_b,
                 float* __restrict__ out)
{
    __shared__ __half rb[2][NPC][RB_STRIDE];     // double-buffered full state
    __shared__ __align__(8) unsigned long long s_mbar;
    __shared__ short s_inp[R_NODES];
    __shared__ int s_innodes[32];
    __shared__ unsigned short s_ph[R_NODES];
    __shared__ float s_W[OUT_DIM * R_NODES];

    const int tid  = threadIdx.x;
    const int wid  = tid >> 5;
    const int lane = tid & 31;
    const int g    = lane >> 2;                  // MMA row-in-tile (also B sample row)
    const int tg   = lane & 3;
    const int rank  = blockIdx.x & 1;
    const int mbase = (blockIdx.x >> 1) * NPC;
    const unsigned short ONE16 = 0x3C00, ZERO16 = 0;
    __half* rbf = &rb[0][0][0];

    // ---- tables ----
    s_inp[tid] = -1;
    s_ph[tid]  = __half_as_ushort(__int2half_rn(primes[tid]));
    for (int i = tid; i < OUT_DIM * R_NODES; i += 256) s_W[i] = readout_W[i];
    if (tid == 0) MBAR_INIT(smem_u32(&s_mbar), 2);
    __syncthreads();
    if (tid < 32) {
        int nn = input_nodes[tid];
        s_innodes[tid] = nn;
        s_inp[nn] = (short)tid;
    }

    // ---- A fragments: warp w owns 16 nodes [rank*128 + w*16, +16), 64 regs ----
    const int node_base = rank * 128 + wid * 16;
    unsigned A[16][4];
    #pragma unroll
    for (int kt = 0; kt < 16; kt++) {
        #pragma unroll
        for (int r = 0; r < 4; r++) {
            int row = node_base + g + ((r & 1) ? 8 : 0);
            int k0  = kt * 16 + tg * 2 + ((r & 2) ? 8 : 0);
            unsigned h0 = Wres[row * 256 + k0]     ? (unsigned)s_ph[k0]     : 0u;
            unsigned h1 = Wres[row * 256 + k0 + 1] ? (unsigned)s_ph[k0 + 1] : 0u;
            A[kt][r] = h0 | (h1 << 16);
        }
    }

    // ---- init full state in rb[0] (both CTAs identical) ----
    {
        __half v = init_res[tid] ? __ushort_as_half(ONE16) : __ushort_as_half(ZERO16);
        #pragma unroll
        for (int s = 0; s < NPC; s++) rb[0][s][tid] = v;
    }
    __syncthreads();
    {
        int s = tid >> 5, i = tid & 31;
        unsigned xb = (g_x_bits[(size_t)(mbase + s) * N_STEPS + 0] >> i) & 1u;
        rb[0][s][s_innodes[i]] = xb ? __ushort_as_half(ONE16) : __ushort_as_half(ZERO16);
    }
    __syncthreads();
    CLUSTER_SYNC();                              // mbarrier + init state visible

    // ---- per-thread constants ----
    const int n0 = node_base + g, n1 = n0 + 8;   // this thread's two nodes
    const bool inp0 = (s_inp[n0] >= 0), inp1 = (s_inp[n1] >= 0);
    const unsigned* lut0 = g_lut_bits + (size_t)n0 * LUT_WORDS;
    const unsigned* lut1 = g_lut_bits + (size_t)n1 * LUT_WORDS;
    const int s0 = tg * 2, s1 = tg * 2 + 1;      // this thread's two samples
    const int xs = tid >> 5, xi = tid & 31;      // x-overwrite role
    const int xnode = s_innodes[xi];
    const unsigned* xrow = g_x_bits + (size_t)(mbase + xs) * N_STEPS;

    const uint32_t rb_local  = smem_u32(rbf);
    const uint32_t rb_remote = mapa_u32(rb_local, rank ^ 1);
    const uint32_t mbar = smem_u32(&s_mbar);
    const uint32_t mbar_remote = mapa_u32(mbar, rank ^ 1);

    // ---- 512 sequential steps ----
    for (int t = 0; t < N_STEPS; t++) {
        const int p = t & 1;
        const bool last = (t == N_STEPS - 1);
        const __half (*cur)[RB_STRIDE] = rb[p];

        // 4-way split accumulators; chunk 0 carries the 2^23 magic offset
        float d[4][4];
        #pragma unroll
        for (int c = 0; c < 4; c++)
            #pragma unroll
            for (int e = 0; e < 4; e++)
                d[c][e] = (c == 0) ? MAGIC_F : 0.0f;

        #pragma unroll
        for (int kt = 0; kt < 16; kt++) {
            unsigned b0 = *(const unsigned*)&cur[g][kt * 16 + tg * 2];
            unsigned b1 = *(const unsigned*)&cur[g][kt * 16 + tg * 2 + 8];
            mma16816(d[kt & 3], A[kt], b0, b1);
        }

        unsigned xw = 0;
        if (!last) xw = xrow[t + 1];             // prefetch next input word

        // indices via magic mantissa (exact)
        unsigned u[4];
        #pragma unroll
        for (int e = 0; e < 4; e++) {
            float tot = (d[0][e] + d[1][e]) + (d[2][e] + d[3][e]);
            u[e] = __float_as_uint(tot) & 0x7FFFFFu;
        }

        // batched LUT gathers (skip input nodes unless last step)
        const bool do0 = last || !inp0;
        const bool do1 = last || !inp1;
        unsigned w[4];
        if (do0) { w[0] = lut0[u[0] >> 5]; w[1] = lut0[u[1] >> 5]; }
        if (do1) { w[2] = lut1[u[2] >> 5]; w[3] = lut1[u[3] >> 5]; }

        // write new state: local + peer (DSMEM), buffer p^1
        const unsigned bufh = (unsigned)((p ^ 1) * NPC) * RB_STRIDE;
        #pragma unroll
        for (int e = 0; e < 4; e++) {
            const bool doe = (e & 2) ? do1 : do0;
            if (doe) {
                int node = (e & 2) ? n1 : n0;
                int samp = (e & 1) ? s1 : s0;
                unsigned short v = ((w[e] >> (u[e] & 31)) & 1u) ? ONE16 : ZERO16;
                unsigned idx_h = bufh + (unsigned)samp * RB_STRIDE + (unsigned)node;
                rbf[idx_h] = __ushort_as_half(v);
                st_cluster_u16(rb_remote + idx_h * 2, v);
            }
        }
        // x_{t+1} into input nodes (local only; both CTAs do this identically)
        if (!last) {
            unsigned short v = ((xw >> xi) & 1u) ? ONE16 : ZERO16;
            rbf[bufh + (unsigned)xs * RB_STRIDE + (unsigned)xnode] = __ushort_as_half(v);
        }

        __syncthreads();                         // all local work + DSMEM stores issued
        if (tid == 0) {
            mbar_arrive_local(mbar);             // release, cluster scope (cumulative)
            mbar_arrive_remote(mbar_remote);
        }
        mbar_wait_cluster(mbar, t & 1);          // acquire, cluster scope
    }

    // ---- readout (rank 0 only): warp w -> sample w; final state in rb[0] ----
    if (rank == 0) {
        float acc[OUT_DIM];
        #pragma unroll
        for (int o = 0; o < OUT_DIM; o++) acc[o] = 0.0f;
        #pragma unroll
        for (int kk = 0; kk < 8; kk++) {
            int k = lane + kk * 32;
            float rv = __half2float(rb[0][wid][k]);
            #pragma unroll
            for (int o = 0; o < OUT_DIM; o++)
                acc[o] += rv * s_W[o * R_NODES + k];
        }
        #pragma unroll
        for (int o = 0; o < OUT_DIM; o++) {
            #pragma unroll
            for (int off = 16; off; off >>= 1)
                acc[o] += __shfl_xor_sync(0xFFFFFFFFu, acc[o], off);
        }
        if (lane == 0) {
            #pragma unroll
            for (int o = 0; o < OUT_DIM; o++)
                out[(mbase + wid) * OUT_DIM + o] = acc[o] + readout_b[o];
        }
    }

    CLUSTER_SYNC();                              // no CTA exits while peer may arrive
}

// ---------------------------------------------------------------------------
// kernel_launch. Inputs: x, input_nodes, lut, W_res, primes, init_res,
// readout_W, readout_b (bool arrays delivered as int32).
// ---------------------------------------------------------------------------
extern "C" void kernel_launch(void* const* d_in, const int* in_sizes, int n_in,
                              void* d_out, int out_size) {
    const int*   x        = (const int*)d_in[0];
    const int*   in_nodes = (const int*)d_in[1];
    const int*   lut      = (const int*)d_in[2];
    const int*   Wres     = (const int*)d_in[3];
    const int*   primes   = (const int*)d_in[4];
    const int*   init_res = (const int*)d_in[5];
    const float* rW       = (const float*)d_in[6];
    const float* rb       = (const float*)d_in[7];
    float*       out      = (float*)d_out;

    pack_lut_kernel<<<(R_NODES * LUT_WORDS) / (32 * 8), 256>>>(lut);
    pack_x_kernel<<<(M_SAMP * N_STEPS) / 256, 256>>>(x);
    reservoir_kernel<<<N_CTA, 256>>>(in_nodes, Wres, primes, init_res, rW, rb, out);
}

// round 7
// speedup vs baseline: 1.4310x; 1.4310x over previous
#include <cuda_runtime.h>
#include <cuda_fp16.h>
#include <stdint.h>

#define R_NODES   256
#define N_STEPS   512
#define M_SAMP    512
#define OUT_DIM   10
#define LUT_WORDS 8192            // 2^18 bits / 32
#define NPC       4               // samples per CTA
#define N_CTA     (M_SAMP / NPC)  // 128 CTAs -> ~1 per SM
#define RB_STRIDE 264             // halfs per row: banks (g*132+tg)%32 distinct
#define MAGIC_F   8388608.0f      // 2^23: accumulator mantissa low 23 bits == integer sum

// Scratch: __device__ globals (no allocation allowed)
__device__ unsigned g_lut_bits[R_NODES * LUT_WORDS]; // 8 MB bit-packed LUT
__device__ unsigned g_x_bits[M_SAMP * N_STEPS];      // 1 MB bit-packed inputs

// ---------------------------------------------------------------------------
// Pack LUT (flat): word w, bit b = lut[w*32 + b]. MLP=32 load stage then ballots.
// ---------------------------------------------------------------------------
__global__ void pack_lut_kernel(const int* __restrict__ lut) {
    const int warp_g = (blockIdx.x * blockDim.x + threadIdx.x) >> 5;
    const int lane   = threadIdx.x & 31;
    const int w0     = warp_g * 32;
    const unsigned* src = (const unsigned*)lut;
    unsigned v[32];
    #pragma unroll
    for (int i = 0; i < 32; i++)
        v[i] = src[(size_t)(w0 + i) * 32 + lane];
    unsigned myw = 0;
    #pragma unroll
    for (int i = 0; i < 32; i++) {
        unsigned b = __ballot_sync(0xFFFFFFFFu, v[i] & 1u);
        if (i == lane) myw = b;
    }
    g_lut_bits[w0 + lane] = myw;
}

// ---------------------------------------------------------------------------
// Pack x: int32[512][512][4][8] (0/1) -> g_x_bits[m*512 + t], bit i = feature i
// ---------------------------------------------------------------------------
__global__ void pack_x_kernel(const int* __restrict__ x) {
    int w = blockIdx.x * blockDim.x + threadIdx.x;
    if (w >= M_SAMP * N_STEPS) return;
    const uint4* p = (const uint4*)(x + (size_t)w * 32);
    unsigned word = 0;
    #pragma unroll
    for (int j = 0; j < 8; j++) {
        uint4 v = p[j];
        word |= (v.x & 1u) << (4 * j + 0);
        word |= (v.y & 1u) << (4 * j + 1);
        word |= (v.z & 1u) << (4 * j + 2);
        word |= (v.w & 1u) << (4 * j + 3);
    }
    g_x_bits[w] = word;
}

// ---------------------------------------------------------------------------
// m16n8k16 fp16 MMA, fp32 accumulate (exact for our integer ranges)
// ---------------------------------------------------------------------------
__device__ __forceinline__ void mma16816(float* d, const unsigned* a, unsigned b0, unsigned b1) {
    asm volatile(
        "mma.sync.aligned.m16n8k16.row.col.f32.f16.f16.f32 "
        "{%0,%1,%2,%3}, {%4,%5,%6,%7}, {%8,%9}, {%0,%1,%2,%3};\n"
        : "+f"(d[0]), "+f"(d[1]), "+f"(d[2]), "+f"(d[3])
        : "r"(a[0]), "r"(a[1]), "r"(a[2]), "r"(a[3]), "r"(b0), "r"(b1));
}

// ---------------------------------------------------------------------------
// Main reservoir kernel: 128 CTAs x 256 threads, CTA b owns samples [4b, 4b+4)
// Warp w owns nodes [32w, 32w+32): A = Wp rows held in 128 registers.
// B tile is 8 rows (m16n8k16 shape); rows 4-7 are permanently zero.
// Gather work lives on threads with (lane&3)<2: 8 scattered L2 loads each.
// ---------------------------------------------------------------------------
__global__ void __launch_bounds__(256, 1)
reservoir_kernel(const int* __restrict__ input_nodes,
                 const int* __restrict__ Wres,
                 const int* __restrict__ primes,
                 const int* __restrict__ init_res,
                 const float* __restrict__ readout_W,
                 const float* __restrict__ readout_b,
                 float* __restrict__ out)
{
    __shared__ __half rb[2][8][RB_STRIDE];       // double-buffered state (8 B-rows)
    __shared__ short s_inp[R_NODES];             // node -> input-feature index or -1
    __shared__ int s_innodes[32];                // feature -> node
    __shared__ unsigned short s_ph[R_NODES];     // primes as fp16 bit patterns
    __shared__ float s_W[OUT_DIM * R_NODES];     // readout weights

    const int tid  = threadIdx.x;
    const int wid  = tid >> 5;
    const int lane = tid & 31;
    const int g    = lane >> 2;                  // MMA row-in-tile / B sample row
    const int tg   = lane & 3;
    const int mbase = blockIdx.x * NPC;
    const __half ONE  = __ushort_as_half(0x3C00);
    const __half ZERO = __ushort_as_half(0x0000);

    // ---- shared tables ----
    s_inp[tid] = -1;
    s_ph[tid]  = __half_as_ushort(__int2half_rn(primes[tid]));
    for (int i = tid; i < OUT_DIM * R_NODES; i += 256) s_W[i] = readout_W[i];
    __syncthreads();
    if (tid < 32) {
        int nn = input_nodes[tid];
        s_innodes[tid] = nn;
        s_inp[nn] = (short)tid;
    }

    // ---- A fragments (Wp = Wres ? prime : 0), register-resident ----
    unsigned A[16][2][4];
    const int node_base = wid * 32;
    #pragma unroll
    for (int kt = 0; kt < 16; kt++) {
        #pragma unroll
        for (int mt = 0; mt < 2; mt++) {
            #pragma unroll
            for (int r = 0; r < 4; r++) {
                int row = node_base + mt * 16 + g + ((r & 1) ? 8 : 0);
                int k0  = kt * 16 + tg * 2 + ((r & 2) ? 8 : 0);
                unsigned h0 = Wres[row * 256 + k0]     ? (unsigned)s_ph[k0]     : 0u;
                unsigned h1 = Wres[row * 256 + k0 + 1] ? (unsigned)s_ph[k0 + 1] : 0u;
                A[kt][mt][r] = h0 | (h1 << 16);
            }
        }
    }

    // ---- init: rows 0-3 = init_res state, rows 4-7 = zero (both buffers) ----
    {
        __half v = init_res[tid] ? ONE : ZERO;
        #pragma unroll
        for (int s = 0; s < NPC; s++) rb[0][s][tid] = v;
        #pragma unroll
        for (int s = NPC; s < 8; s++) { rb[0][s][tid] = ZERO; rb[1][s][tid] = ZERO; }
    }
    __syncthreads();
    if (tid < NPC * 32) {
        int s = tid >> 5, i = tid & 31;          // sample s, feature i
        unsigned xb = (g_x_bits[(size_t)(mbase + s) * N_STEPS + 0] >> i) & 1u;
        rb[0][s][s_innodes[i]] = xb ? ONE : ZERO;
    }
    __syncthreads();

    // ---- per-thread gather constants (active: tg < 2) ----
    const bool active = (tg < 2);
    const unsigned* lp[2][2];                    // [mt][rowhalf] LUT row base
    int nodes[2][2];
    bool is_inp[2][2];
    #pragma unroll
    for (int mt = 0; mt < 2; mt++)
        #pragma unroll
        for (int h = 0; h < 2; h++) {
            int n = node_base + mt * 16 + g + h * 8;
            nodes[mt][h]  = n;
            lp[mt][h]     = g_lut_bits + (size_t)n * LUT_WORDS;
            is_inp[mt][h] = (s_inp[n] >= 0);
        }
    const int xs = tid >> 5;                     // x-overwrite role (threads < 128)
    const int xi = tid & 31;
    const int xnode = (tid < NPC * 32) ? s_innodes[xi] : 0;
    const unsigned* xrow = g_x_bits + (size_t)(mbase + (xs & (NPC - 1))) * N_STEPS;

    // ---- 512 sequential steps, one barrier per step ----
    for (int t = 0; t < N_STEPS; t++) {
        const int p = t & 1;
        const bool last = (t == N_STEPS - 1);
        const __half (*cur)[RB_STRIDE] = rb[p];
        __half (*nxt)[RB_STRIDE] = rb[p ^ 1];

        // prefetch next input word while MMAs run
        unsigned xw = 0;
        if (!last && tid < NPC * 32) xw = xrow[t + 1];

        // 4-way split accumulators; chunk 0 carries the 2^23 magic offset
        float d[2][4][4];
        #pragma unroll
        for (int mt = 0; mt < 2; mt++)
            #pragma unroll
            for (int c = 0; c < 4; c++)
                #pragma unroll
                for (int e = 0; e < 4; e++)
                    d[mt][c][e] = (c == 0) ? MAGIC_F : 0.0f;

        #pragma unroll
        for (int kt = 0; kt < 16; kt++) {
            unsigned b0 = *(const unsigned*)&cur[g][kt * 16 + tg * 2];
            unsigned b1 = *(const unsigned*)&cur[g][kt * 16 + tg * 2 + 8];
            mma16816(d[0][kt & 3], A[kt][0], b0, b1);
            mma16816(d[1][kt & 3], A[kt][1], b0, b1);
        }

        if (active) {
            // indices via magic mantissa (exact integer sums)
            unsigned u[2][4];
            #pragma unroll
            for (int mt = 0; mt < 2; mt++)
                #pragma unroll
                for (int e = 0; e < 4; e++) {
                    float tot = (d[mt][0][e] + d[mt][1][e]) + (d[mt][2][e] + d[mt][3][e]);
                    u[mt][e] = __float_as_uint(tot) & 0x7FFFFFu;
                }

            // batch up to 8 LUT word loads (skip input nodes unless last step)
            unsigned w[2][4];
            #pragma unroll
            for (int mt = 0; mt < 2; mt++)
                #pragma unroll
                for (int e = 0; e < 4; e++)
                    if (last || !is_inp[mt][e >> 1])
                        w[mt][e] = lp[mt][e >> 1][u[mt][e] >> 5];

            #pragma unroll
            for (int mt = 0; mt < 2; mt++)
                #pragma unroll
                for (int e = 0; e < 4; e++)
                    if (last || !is_inp[mt][e >> 1]) {
                        int samp = tg * 2 + (e & 1);     // 0..3 since tg<2
                        nxt[samp][nodes[mt][e >> 1]] =
                            ((w[mt][e] >> (u[mt][e] & 31)) & 1u) ? ONE : ZERO;
                    }
        }

        // x_{t+1} into input nodes of next buffer (threads 0..127: 4 samples x 32 feats)
        if (!last && tid < NPC * 32)
            nxt[xs][xnode] = ((xw >> xi) & 1u) ? ONE : ZERO;

        __syncthreads();
    }

    // ---- readout: warps 0-3, warp w -> sample w; final state in rb[0] ----
    if (wid < NPC) {
        float acc[OUT_DIM];
        #pragma unroll
        for (int o = 0; o < OUT_DIM; o++) acc[o] = 0.0f;
        #pragma unroll
        for (int kk = 0; kk < 8; kk++) {
            int k = lane + kk * 32;
            float rv = __half2float(rb[0][wid][k]);
            #pragma unroll
            for (int o = 0; o < OUT_DIM; o++)
                acc[o] += rv * s_W[o * R_NODES + k];
        }
        #pragma unroll
        for (int o = 0; o < OUT_DIM; o++) {
            #pragma unroll
            for (int off = 16; off; off >>= 1)
                acc[o] += __shfl_xor_sync(0xFFFFFFFFu, acc[o], off);
        }
        if (lane == 0) {
            #pragma unroll
            for (int o = 0; o < OUT_DIM; o++)
                out[(mbase + wid) * OUT_DIM + o] = acc[o] + readout_b[o];
        }
    }
}

// ---------------------------------------------------------------------------
// kernel_launch. Inputs: x, input_nodes, lut, W_res, primes, init_res,
// readout_W, readout_b (bool arrays delivered as int32).
// ---------------------------------------------------------------------------
extern "C" void kernel_launch(void* const* d_in, const int* in_sizes, int n_in,
                              void* d_out, int out_size) {
    const int*   x        = (const int*)d_in[0];
    const int*   in_nodes = (const int*)d_in[1];
    const int*   lut      = (const int*)d_in[2];
    const int*   Wres     = (const int*)d_in[3];
    const int*   primes   = (const int*)d_in[4];
    const int*   init_res = (const int*)d_in[5];
    const float* rW       = (const float*)d_in[6];
    const float* rb       = (const float*)d_in[7];
    float*       out      = (float*)d_out;

    pack_lut_kernel<<<(R_NODES * LUT_WORDS) / (32 * 8), 256>>>(lut);
    pack_x_kernel<<<(M_SAMP * N_STEPS) / 256, 256>>>(x);
    reservoir_kernel<<<N_CTA, 256>>>(in_nodes, Wres, primes, init_res, rW, rb, out);
}